// round 10
// baseline (speedup 1.0000x reference)
#include <cuda_runtime.h>
#include <cstdint>

// Problem constants (from reference setup_inputs)
#define MAXB   32
#define MAXN   131072
#define TILE   1024          // points per CTA (24.6KB smem -> 8 CTAs/SM)
#define TPB    256           // threads per CTA
#define PPT    4             // points per thread (TILE / TPB)
#define MAXTILES (MAXN / TILE)   // 128
#define NWARP  (TPB / 32)
#define NCELL  (PPT * NWARP)     // 32 cells -> one-per-lane warp scan

#define SMEM_TILE_FLOATS (TILE * 6)

// Scratch (allocation-free rule: __device__ globals). ~96 MiB staging buffer:
// tile t of batch b stages its compacted valid rows at rows [t*TILE, t*TILE+cnt).
__device__ float        g_scratch[(size_t)MAXB * MAXN * 6];
__device__ unsigned int g_cnt[MAXB * MAXTILES];

// Validity: bit-matches the JAX reference (verified rel_err=0.0 R3-R9).
// DO NOT change the op order / non-FMA structure.
__device__ __forceinline__ bool is_valid(float x, float y, float z,
                                         float nx, float ny, float nz,
                                         const float* __restrict__ T) {
    float px = __fadd_rn(__fadd_rn(__fadd_rn(__fmul_rn(x, T[0]), __fmul_rn(y, T[4])), __fmul_rn(z, T[8])),  T[3]);
    float py = __fadd_rn(__fadd_rn(__fadd_rn(__fmul_rn(x, T[1]), __fmul_rn(y, T[5])), __fmul_rn(z, T[9])),  T[7]);
    float pz = __fadd_rn(__fadd_rn(__fadd_rn(__fmul_rn(x, T[2]), __fmul_rn(y, T[6])), __fmul_rn(z, T[10])), T[11]);
    float sq = __fadd_rn(__fmul_rn(px, px), __fmul_rn(py, py));
    float ns = __fadd_rn(__fadd_rn(nx, ny), nz);
    return (sq < 1.0f) && (pz < 1.0f) && (ns != 0.0f);
}

// ---------------------------------------------------------------------------
// Kernel 1: stage. Per tile: classify, rank, write count + compacted valid
// rows into g_scratch at the tile's own base. NO inter-CTA communication.
// Valid rows are RE-READ FROM SMEM at scatter time (no register tile cache)
// to keep register pressure low -> 8 CTAs/SM.
// Stable rank: point p = i*TPB + tid == order (i, tid); cell k = i*NWARP+wid
// covers a contiguous 32-point block in increasing p (verified R4/R6/R8).
// ---------------------------------------------------------------------------
__global__ void __launch_bounds__(TPB) stage_kernel(const float* __restrict__ pc,
                                                    const float* __restrict__ tf,
                                                    int N, int tiles) {
    __shared__ float sTile[SMEM_TILE_FLOATS];
    __shared__ unsigned int sScan[NCELL];

    const int b    = blockIdx.y;
    const int tile = blockIdx.x;
    const int tid  = threadIdx.x;
    const int lane = tid & 31;
    const int wid  = tid >> 5;
    const float* __restrict__ T = tf + (size_t)b * 16;

    const size_t batch_base = (size_t)b * N;
    const int tile_base = tile * TILE;

    // --- coalesced tile load; .cs (read-once) protects scratch L2 residency ---
    {
        const float4* __restrict__ gsrc =
            (const float4*)(pc + (batch_base + tile_base) * 6);
        float4* s4 = (float4*)sTile;
#pragma unroll
        for (int i = 0; i < SMEM_TILE_FLOATS / 4 / TPB; i++)
            s4[tid + i * TPB] = __ldcs(gsrc + tid + i * TPB);
    }
    __syncthreads();

    // --- classify from smem (no register cache of the data) ---
    unsigned int vbits = 0;
    {
        const float2* s2 = (const float2*)sTile;
#pragma unroll
        for (int i = 0; i < PPT; i++) {
            const int p = tid + i * TPB;
            const float2 q0 = s2[p * 3 + 0];
            const float2 q1 = s2[p * 3 + 1];
            const float2 q2 = s2[p * 3 + 2];
            bool v = is_valid(q0.x, q0.y, q1.x, q1.y, q2.x, q2.y, T);
            vbits |= (v ? 1u : 0u) << i;
        }
    }

    // --- ballots -> 32 cell counts ---
    unsigned int ball[PPT];
#pragma unroll
    for (int i = 0; i < PPT; i++) {
        ball[i] = __ballot_sync(0xFFFFFFFFu, (vbits >> i) & 1u);
        if (lane == 0) sScan[i * NWARP + wid] = __popc(ball[i]);
    }
    __syncthreads();

    // --- warp 0: exclusive scan of 32 cells (one per lane), publish count ---
    if (wid == 0) {
        const unsigned int v = sScan[lane];
        unsigned int x = v;
#pragma unroll
        for (int o = 1; o < 32; o <<= 1) {
            unsigned int y = __shfl_up_sync(0xFFFFFFFFu, x, o);
            if (lane >= o) x += y;
        }
        sScan[lane] = x - v;                               // exclusive
        if (lane == 31) g_cnt[b * tiles + tile] = x;
    }
    __syncthreads();

    // --- scatter valid rows: smem -> scratch (only ~10% of points) ---
    const unsigned int lmask = (1u << lane) - 1u;
    float2* __restrict__ gdst = (float2*)(g_scratch + (batch_base + tile_base) * 6);
    const float2* s2 = (const float2*)sTile;
#pragma unroll
    for (int i = 0; i < PPT; i++) {
        if ((vbits >> i) & 1u) {
            const int p = tid + i * TPB;
            const unsigned int rank = sScan[i * NWARP + wid] + __popc(ball[i] & lmask);
            gdst[rank * 3 + 0] = s2[p * 3 + 0];
            gdst[rank * 3 + 1] = s2[p * 3 + 1];
            gdst[rank * 3 + 2] = s2[p * 3 + 2];
        }
    }
}

// ---------------------------------------------------------------------------
// Kernel 2: gather + zero. Warp 0 redundantly scans the batch's 128 counts
// (L2-hot, 512B, 4 cells/lane) -> exact prefix & K_b, no spinning. Then:
//   copy scratch[tile_base .. +cnt) -> out[prefix .. +cnt)   (L2-hit reads)
//   zero out rows in this tile's output slice that fall in [K_b, N)
// Copy uses float4 when the destination is 16B-aligned (prefix even).
// ---------------------------------------------------------------------------
__global__ void __launch_bounds__(TPB) gather_zero_kernel(float* __restrict__ out,
                                                          int N, int tiles) {
    __shared__ unsigned int sMeta[3];   // [0]=prefix, [1]=K_b, [2]=cnt

    const int b    = blockIdx.y;
    const int tile = blockIdx.x;
    const int tid  = threadIdx.x;
    const int lane = tid & 31;
    const int wid  = tid >> 5;
    const size_t batch_base = (size_t)b * N;

    if (wid == 0) {
        // 128 counts, 4 per lane (requires tiles == 128)
        unsigned int c[4];
#pragma unroll
        for (int j = 0; j < 4; j++) c[j] = g_cnt[b * tiles + 4 * lane + j];
        const unsigned int s = c[0] + c[1] + c[2] + c[3];
        unsigned int x = s;
#pragma unroll
        for (int o = 1; o < 32; o <<= 1) {
            unsigned int y = __shfl_up_sync(0xFFFFFFFFu, x, o);
            if (lane >= o) x += y;
        }
        const unsigned int excl  = x - s;
        const unsigned int total = __shfl_sync(0xFFFFFFFFu, x, 31);
        const int sl = tile >> 2;                          // source lane
        unsigned int p0 = __shfl_sync(0xFFFFFFFFu, excl, sl);
        unsigned int k0 = __shfl_sync(0xFFFFFFFFu, c[0], sl);
        unsigned int k1 = __shfl_sync(0xFFFFFFFFu, c[1], sl);
        unsigned int k2 = __shfl_sync(0xFFFFFFFFu, c[2], sl);
        unsigned int k3 = __shfl_sync(0xFFFFFFFFu, c[3], sl);
        if (lane == 0) {
            const int j = tile & 3;
            unsigned int pref = p0;
            unsigned int kk[4] = {k0, k1, k2, k3};
            for (int t = 0; t < j; t++) pref += kk[t];
            sMeta[0] = pref;
            sMeta[1] = total;
            sMeta[2] = kk[j];
        }
    }
    __syncthreads();
    const unsigned int prefix = sMeta[0];
    const unsigned int Kb     = sMeta[1];
    const unsigned int cnt    = sMeta[2];

    // --- copy valid block: scratch (L2-resident) -> final position ---
    {
        const float* __restrict__ srcf =
            g_scratch + (batch_base + (size_t)tile * TILE) * 6;
        float* __restrict__ dstf = out + (batch_base + prefix) * 6;
        const unsigned int nF = cnt * 6;                   // floats to copy
        if ((prefix & 1u) == 0u) {
            const float4* __restrict__ s4 = (const float4*)srcf;
            float4* __restrict__ d4 = (float4*)dstf;
            const unsigned int nF4 = nF >> 2;
            for (unsigned int i = tid; i < nF4; i += TPB)
                __stcs(d4 + i, s4[i]);
            if (tid == 0 && (nF & 3u))                     // cnt odd: 2 floats left
                __stcs((float2*)(dstf + (nF4 << 2)),
                       *(const float2*)(srcf + (nF4 << 2)));
        } else {
            const float2* __restrict__ s2 = (const float2*)srcf;
            float2* __restrict__ d2 = (float2*)dstf;
            const unsigned int nF2 = nF >> 1;
            for (unsigned int i = tid; i < nF2; i += TPB)
                __stcs(d2 + i, s2[i]);
        }
    }

    // --- zero this tile's share of the tail [K_b, N) ---
    const long long Kf = (long long)Kb * 6;
    const long long f0 = (long long)tile * TILE * 6;
    const long long f1 = f0 + (long long)TILE * 6;         // multiple of 4
    long long lo = Kf > f0 ? Kf : f0;
    if (lo >= f1) return;
    float* base = out + batch_base * 6;                    // 16B-aligned
    const long long lo4 = (lo + 3) & ~3LL;                 // align head
    if (tid < (int)(lo4 - lo)) base[lo + tid] = 0.0f;
    float4* b4 = (float4*)base;
    const float4 z4 = make_float4(0.0f, 0.0f, 0.0f, 0.0f);
    for (long long i = (lo4 >> 2) + tid; i < (f1 >> 2); i += TPB)
        __stcs(b4 + i, z4);
}

// ---------------------------------------------------------------------------
extern "C" void kernel_launch(void* const* d_in, const int* in_sizes, int n_in,
                              void* d_out, int out_size) {
    const float* pc = (const float*)d_in[0];   // pointclouds (B, N, 6)
    const float* tf = (const float*)d_in[1];   // task_transform (B, 4, 4)

    const int B = in_sizes[1] / 16;
    const int N = (int)((long long)in_sizes[0] / (6LL * B));
    const int tiles = N / TILE;               // 128

    dim3 grid(tiles, B);
    stage_kernel<<<grid, TPB>>>(pc, tf, N, tiles);
    gather_zero_kernel<<<grid, TPB>>>((float*)d_out, N, tiles);
}

// round 11
// speedup vs baseline: 1.1353x; 1.1353x over previous
#include <cuda_runtime.h>
#include <cstdint>

// Problem constants (from reference setup_inputs)
#define MAXB   32
#define MAXN   131072
#define TILE   2048          // points per CTA
#define TPB    256           // threads per CTA
#define NPAIR  4             // 4 pair-iterations x 2 points = 8 points/thread
#define MAXTILES (MAXN / TILE)   // 64
#define NWARP  (TPB / 32)
#define NCELL  (NPAIR * NWARP)   // 32 cells (64-point blocks) -> warp scan

// Scratch (allocation-free rule: __device__ globals). ~96 MiB staging buffer:
// tile t of batch b stages its compacted valid rows at rows [t*TILE, t*TILE+cnt).
__device__ float        g_scratch[(size_t)MAXB * MAXN * 6];
__device__ unsigned int g_cnt[MAXB * MAXTILES];

// Validity: bit-matches the JAX reference (verified rel_err=0.0 R3-R10).
// DO NOT change the op order / non-FMA structure.
__device__ __forceinline__ bool is_valid(float x, float y, float z,
                                         float nx, float ny, float nz,
                                         const float* __restrict__ T) {
    float px = __fadd_rn(__fadd_rn(__fadd_rn(__fmul_rn(x, T[0]), __fmul_rn(y, T[4])), __fmul_rn(z, T[8])),  T[3]);
    float py = __fadd_rn(__fadd_rn(__fadd_rn(__fmul_rn(x, T[1]), __fmul_rn(y, T[5])), __fmul_rn(z, T[9])),  T[7]);
    float pz = __fadd_rn(__fadd_rn(__fadd_rn(__fmul_rn(x, T[2]), __fmul_rn(y, T[6])), __fmul_rn(z, T[10])), T[11]);
    float sq = __fadd_rn(__fmul_rn(px, px), __fmul_rn(py, py));
    float ns = __fadd_rn(__fadd_rn(nx, ny), nz);
    return (sq < 1.0f) && (pz < 1.0f) && (ns != 0.0f);
}

// ---------------------------------------------------------------------------
// Kernel 1: stage. Direct global->register loads (48B/thread stride: 3 float4
// = 2 consecutive points), classify, dual-ballot rank, scatter valid rows to
// g_scratch at the tile's own base. NO smem tile, NO inter-CTA communication.
//
// Point mapping: iter j, warp w, lane l, sub m  ->  p = j*512 + w*64 + 2l + m.
// Warp w's iter-j block = contiguous points [j*512+w*64, +64); in-block order
// is 2l+m. Cell j*8+w covers that block; cells ascend with point order.
// ---------------------------------------------------------------------------
__global__ void __launch_bounds__(TPB) stage_kernel(const float* __restrict__ pc,
                                                    const float* __restrict__ tf,
                                                    int N, int tiles) {
    __shared__ unsigned int sScan[NCELL];

    const int b    = blockIdx.y;
    const int tile = blockIdx.x;
    const int tid  = threadIdx.x;
    const int lane = tid & 31;
    const int wid  = tid >> 5;
    const float* __restrict__ T = tf + (size_t)b * 16;

    const size_t batch_base = (size_t)b * N;
    const int tile_base = tile * TILE;

    // --- direct loads: 3 consecutive float4 per thread per iter (.cs) ---
    const float4* __restrict__ gsrc =
        (const float4*)(pc + (batch_base + tile_base) * 6);
    float4 d[NPAIR][3];
#pragma unroll
    for (int j = 0; j < NPAIR; j++) {
        const int f4 = j * 768 + 3 * tid;      // 512 points = 768 float4 per iter
        d[j][0] = __ldcs(gsrc + f4 + 0);
        d[j][1] = __ldcs(gsrc + f4 + 1);
        d[j][2] = __ldcs(gsrc + f4 + 2);
    }

    // --- classify: 2 points per iter ---
    unsigned int v0bits = 0, v1bits = 0;
#pragma unroll
    for (int j = 0; j < NPAIR; j++) {
        const float4 A = d[j][0], B = d[j][1], C = d[j][2];
        if (is_valid(A.x, A.y, A.z, A.w, B.x, B.y, T)) v0bits |= 1u << j;
        if (is_valid(B.z, B.w, C.x, C.y, C.z, C.w, T)) v1bits |= 1u << j;
    }

    // --- dual ballots per iter -> 32 cell counts ---
    unsigned int b0[NPAIR], b1[NPAIR];
#pragma unroll
    for (int j = 0; j < NPAIR; j++) {
        b0[j] = __ballot_sync(0xFFFFFFFFu, (v0bits >> j) & 1u);
        b1[j] = __ballot_sync(0xFFFFFFFFu, (v1bits >> j) & 1u);
        if (lane == 0) sScan[j * NWARP + wid] = __popc(b0[j]) + __popc(b1[j]);
    }
    __syncthreads();

    // --- warp 0: exclusive scan of 32 cells, publish tile count ---
    if (wid == 0) {
        const unsigned int v = sScan[lane];
        unsigned int x = v;
#pragma unroll
        for (int o = 1; o < 32; o <<= 1) {
            unsigned int y = __shfl_up_sync(0xFFFFFFFFu, x, o);
            if (lane >= o) x += y;
        }
        sScan[lane] = x - v;                               // exclusive
        if (lane == 31) g_cnt[b * tiles + tile] = x;
    }
    __syncthreads();

    // --- scatter valid rows from registers to scratch ---
    const unsigned int below = (1u << lane) - 1u;
    float2* __restrict__ gdst = (float2*)(g_scratch + (batch_base + tile_base) * 6);
#pragma unroll
    for (int j = 0; j < NPAIR; j++) {
        const unsigned int excl = sScan[j * NWARP + wid];
        const unsigned int p0   = __popc(b0[j] & below);
        const unsigned int p1   = __popc(b1[j] & below);
        const float4 A = d[j][0], B = d[j][1], C = d[j][2];
        if ((v0bits >> j) & 1u) {
            const unsigned int r = excl + p0 + p1;         // in-block 2l+m order
            gdst[r * 3 + 0] = make_float2(A.x, A.y);
            gdst[r * 3 + 1] = make_float2(A.z, A.w);
            gdst[r * 3 + 2] = make_float2(B.x, B.y);
        }
        if ((v1bits >> j) & 1u) {
            const unsigned int r = excl + p0 + ((v0bits >> j) & 1u) + p1;
            gdst[r * 3 + 0] = make_float2(B.z, B.w);
            gdst[r * 3 + 1] = make_float2(C.x, C.y);
            gdst[r * 3 + 2] = make_float2(C.z, C.w);
        }
    }
}

// ---------------------------------------------------------------------------
// Kernel 2: gather + zero (R9 version — measured at its store-path floor).
// Warp 0 redundantly scans the batch's 64 counts -> exact prefix & K_b.
//   copy scratch[tile_base .. +cnt) -> out[prefix .. +cnt)   (L2-hit reads)
//   zero out rows in this tile's output slice that fall in [K_b, N)
// ---------------------------------------------------------------------------
__global__ void __launch_bounds__(TPB) gather_zero_kernel(float* __restrict__ out,
                                                          int N, int tiles) {
    __shared__ unsigned int sMeta[3];   // [0]=prefix, [1]=K_b, [2]=cnt

    const int b    = blockIdx.y;
    const int tile = blockIdx.x;
    const int tid  = threadIdx.x;
    const int lane = tid & 31;
    const int wid  = tid >> 5;
    const size_t batch_base = (size_t)b * N;

    if (wid == 0) {
        const unsigned int c0 = g_cnt[b * tiles + 2 * lane];
        const unsigned int c1 = g_cnt[b * tiles + 2 * lane + 1];
        unsigned int s = c0 + c1;
        unsigned int x = s;
#pragma unroll
        for (int o = 1; o < 32; o <<= 1) {
            unsigned int y = __shfl_up_sync(0xFFFFFFFFu, x, o);
            if (lane >= o) x += y;
        }
        const unsigned int excl  = x - s;
        const unsigned int total = __shfl_sync(0xFFFFFFFFu, x, 31);
        const unsigned int pe  = __shfl_sync(0xFFFFFFFFu, excl, tile >> 1);
        const unsigned int po  = __shfl_sync(0xFFFFFFFFu, excl + c0, tile >> 1);
        const unsigned int mcE = __shfl_sync(0xFFFFFFFFu, c0, tile >> 1);
        const unsigned int mcO = __shfl_sync(0xFFFFFFFFu, c1, tile >> 1);
        if (lane == 0) {
            sMeta[0] = (tile & 1) ? po  : pe;
            sMeta[1] = total;
            sMeta[2] = (tile & 1) ? mcO : mcE;
        }
    }
    __syncthreads();
    const unsigned int prefix = sMeta[0];
    const unsigned int Kb     = sMeta[1];
    const unsigned int cnt    = sMeta[2];

    // --- copy valid block: scratch (L2-resident) -> final position ---
    {
        const float* __restrict__ srcf =
            g_scratch + (batch_base + (size_t)tile * TILE) * 6;
        float* __restrict__ dstf = out + (batch_base + prefix) * 6;
        const unsigned int nF = cnt * 6;                   // floats to copy
        if ((prefix & 1u) == 0u) {
            const float4* __restrict__ s4 = (const float4*)srcf;
            float4* __restrict__ d4 = (float4*)dstf;
            const unsigned int nF4 = nF >> 2;
            for (unsigned int i = tid; i < nF4; i += TPB)
                __stcs(d4 + i, s4[i]);
            if (tid == 0 && (nF & 3u))                     // cnt odd: 2 floats left
                __stcs((float2*)(dstf + (nF4 << 2)),
                       *(const float2*)(srcf + (nF4 << 2)));
        } else {
            const float2* __restrict__ s2 = (const float2*)srcf;
            float2* __restrict__ d2 = (float2*)dstf;
            const unsigned int nF2 = nF >> 1;
            for (unsigned int i = tid; i < nF2; i += TPB)
                __stcs(d2 + i, s2[i]);
        }
    }

    // --- zero this tile's share of the tail [K_b, N) ---
    const long long Kf = (long long)Kb * 6;
    const long long f0 = (long long)tile * TILE * 6;
    const long long f1 = f0 + (long long)TILE * 6;         // multiple of 4
    long long lo = Kf > f0 ? Kf : f0;
    if (lo >= f1) return;
    float* base = out + batch_base * 6;                    // 16B-aligned
    const long long lo4 = (lo + 3) & ~3LL;                 // align head
    if (tid < (int)(lo4 - lo)) base[lo + tid] = 0.0f;
    float4* b4 = (float4*)base;
    const float4 z4 = make_float4(0.0f, 0.0f, 0.0f, 0.0f);
    for (long long i = (lo4 >> 2) + tid; i < (f1 >> 2); i += TPB)
        __stcs(b4 + i, z4);
}

// ---------------------------------------------------------------------------
extern "C" void kernel_launch(void* const* d_in, const int* in_sizes, int n_in,
                              void* d_out, int out_size) {
    const float* pc = (const float*)d_in[0];   // pointclouds (B, N, 6)
    const float* tf = (const float*)d_in[1];   // task_transform (B, 4, 4)

    const int B = in_sizes[1] / 16;
    const int N = (int)((long long)in_sizes[0] / (6LL * B));
    const int tiles = N / TILE;               // 64

    dim3 grid(tiles, B);
    stage_kernel<<<grid, TPB>>>(pc, tf, N, tiles);
    gather_zero_kernel<<<grid, TPB>>>((float*)d_out, N, tiles);
}

// round 12
// speedup vs baseline: 1.1429x; 1.0067x over previous
#include <cuda_runtime.h>
#include <cstdint>

// Problem constants (from reference setup_inputs)
#define MAXB   32
#define MAXN   131072
#define TILE   2048          // points per CTA
#define TPB    256           // threads per CTA
#define NPAIR  4             // 4 pair-iterations x 2 points = 8 points/thread
#define MAXTILES (MAXN / TILE)   // 64
#define NWARP  (TPB / 32)
#define NCELL  (NPAIR * NWARP)   // 32 cells (64-point blocks) -> warp scan

// Scratch (allocation-free rule: __device__ globals). ~96 MiB staging buffer:
// tile t of batch b stages its compacted valid rows at rows [t*TILE, t*TILE+cnt).
__device__ float        g_scratch[(size_t)MAXB * MAXN * 6];
__device__ unsigned int g_cnt[MAXB * MAXTILES];

// Validity: bit-matches the JAX reference (verified rel_err=0.0 R3-R11).
// DO NOT change the op order / non-FMA structure.
__device__ __forceinline__ bool is_valid(float x, float y, float z,
                                         float nx, float ny, float nz,
                                         const float* __restrict__ T) {
    float px = __fadd_rn(__fadd_rn(__fadd_rn(__fmul_rn(x, T[0]), __fmul_rn(y, T[4])), __fmul_rn(z, T[8])),  T[3]);
    float py = __fadd_rn(__fadd_rn(__fadd_rn(__fmul_rn(x, T[1]), __fmul_rn(y, T[5])), __fmul_rn(z, T[9])),  T[7]);
    float pz = __fadd_rn(__fadd_rn(__fadd_rn(__fmul_rn(x, T[2]), __fmul_rn(y, T[6])), __fmul_rn(z, T[10])), T[11]);
    float sq = __fadd_rn(__fmul_rn(px, px), __fmul_rn(py, py));
    float ns = __fadd_rn(__fadd_rn(nx, ny), nz);
    return (sq < 1.0f) && (pz < 1.0f) && (ns != 0.0f);
}

// ---------------------------------------------------------------------------
// Kernel 1: stage. Direct global->register loads (48B/thread: 3 float4 = 2
// consecutive points), classify, dual-ballot rank, scatter valid rows to
// g_scratch, AND zero this tile's entire output slice (valid prefix rows are
// overwritten by gather afterwards -> zeroing needs no prefix information).
// Read(100MB) + zero-write(100MB) overlap in DRAM within one kernel.
//
// Point mapping: iter j, warp w, lane l, sub m  ->  p = j*512 + w*64 + 2l + m.
// Cell j*8+w covers contiguous points [j*512+w*64, +64); in-block order 2l+m.
// ---------------------------------------------------------------------------
__global__ void __launch_bounds__(TPB) stage_kernel(const float* __restrict__ pc,
                                                    const float* __restrict__ tf,
                                                    float* __restrict__ out,
                                                    int N, int tiles) {
    __shared__ unsigned int sScan[NCELL];

    const int b    = blockIdx.y;
    const int tile = blockIdx.x;
    const int tid  = threadIdx.x;
    const int lane = tid & 31;
    const int wid  = tid >> 5;
    const float* __restrict__ T = tf + (size_t)b * 16;

    const size_t batch_base = (size_t)b * N;
    const int tile_base = tile * TILE;

    // --- direct loads: 3 consecutive float4 per thread per iter (.cs) ---
    const float4* __restrict__ gsrc =
        (const float4*)(pc + (batch_base + tile_base) * 6);
    float4 d[NPAIR][3];
#pragma unroll
    for (int j = 0; j < NPAIR; j++) {
        const int f4 = j * 768 + 3 * tid;      // 512 points = 768 float4 per iter
        d[j][0] = __ldcs(gsrc + f4 + 0);
        d[j][1] = __ldcs(gsrc + f4 + 1);
        d[j][2] = __ldcs(gsrc + f4 + 2);
    }

    // --- zero this tile's output slice (independent of loads; overlaps) ---
    {
        float4* __restrict__ zdst = (float4*)(out + (batch_base + tile_base) * 6);
        const float4 z4 = make_float4(0.0f, 0.0f, 0.0f, 0.0f);
#pragma unroll
        for (int i = 0; i < TILE * 6 / 4 / TPB; i++)       // 12 float4/thread
            __stcs(zdst + tid + i * TPB, z4);
    }

    // --- classify: 2 points per iter ---
    unsigned int v0bits = 0, v1bits = 0;
#pragma unroll
    for (int j = 0; j < NPAIR; j++) {
        const float4 A = d[j][0], B = d[j][1], C = d[j][2];
        if (is_valid(A.x, A.y, A.z, A.w, B.x, B.y, T)) v0bits |= 1u << j;
        if (is_valid(B.z, B.w, C.x, C.y, C.z, C.w, T)) v1bits |= 1u << j;
    }

    // --- dual ballots per iter -> 32 cell counts ---
    unsigned int b0[NPAIR], b1[NPAIR];
#pragma unroll
    for (int j = 0; j < NPAIR; j++) {
        b0[j] = __ballot_sync(0xFFFFFFFFu, (v0bits >> j) & 1u);
        b1[j] = __ballot_sync(0xFFFFFFFFu, (v1bits >> j) & 1u);
        if (lane == 0) sScan[j * NWARP + wid] = __popc(b0[j]) + __popc(b1[j]);
    }
    __syncthreads();

    // --- warp 0: exclusive scan of 32 cells, publish tile count ---
    if (wid == 0) {
        const unsigned int v = sScan[lane];
        unsigned int x = v;
#pragma unroll
        for (int o = 1; o < 32; o <<= 1) {
            unsigned int y = __shfl_up_sync(0xFFFFFFFFu, x, o);
            if (lane >= o) x += y;
        }
        sScan[lane] = x - v;                               // exclusive
        if (lane == 31) g_cnt[b * tiles + tile] = x;
    }
    __syncthreads();

    // --- scatter valid rows from registers to scratch (default policy: L2) ---
    const unsigned int below = (1u << lane) - 1u;
    float2* __restrict__ gdst = (float2*)(g_scratch + (batch_base + tile_base) * 6);
#pragma unroll
    for (int j = 0; j < NPAIR; j++) {
        const unsigned int excl = sScan[j * NWARP + wid];
        const unsigned int p0   = __popc(b0[j] & below);
        const unsigned int p1   = __popc(b1[j] & below);
        const float4 A = d[j][0], B = d[j][1], C = d[j][2];
        if ((v0bits >> j) & 1u) {
            const unsigned int r = excl + p0 + p1;         // in-block 2l+m order
            gdst[r * 3 + 0] = make_float2(A.x, A.y);
            gdst[r * 3 + 1] = make_float2(A.z, A.w);
            gdst[r * 3 + 2] = make_float2(B.x, B.y);
        }
        if ((v1bits >> j) & 1u) {
            const unsigned int r = excl + p0 + ((v0bits >> j) & 1u) + p1;
            gdst[r * 3 + 0] = make_float2(B.z, B.w);
            gdst[r * 3 + 1] = make_float2(C.x, C.y);
            gdst[r * 3 + 2] = make_float2(C.z, C.w);
        }
    }
}

// ---------------------------------------------------------------------------
// Kernel 2: gather. Warp 0 redundantly scans the batch's 64 counts (L2-hot)
// -> exact prefix; copy scratch[tile_base .. +cnt) -> out[prefix .. +cnt)
// (scratch reads are L2-hit; ~10MB total). Zero tail already written by stage.
// ---------------------------------------------------------------------------
__global__ void __launch_bounds__(TPB) gather_kernel(float* __restrict__ out,
                                                     int N, int tiles) {
    __shared__ unsigned int sMeta[2];   // [0]=prefix, [1]=cnt

    const int b    = blockIdx.y;
    const int tile = blockIdx.x;
    const int tid  = threadIdx.x;
    const int lane = tid & 31;
    const int wid  = tid >> 5;
    const size_t batch_base = (size_t)b * N;

    if (wid == 0) {
        const unsigned int c0 = g_cnt[b * tiles + 2 * lane];
        const unsigned int c1 = g_cnt[b * tiles + 2 * lane + 1];
        unsigned int s = c0 + c1;
        unsigned int x = s;
#pragma unroll
        for (int o = 1; o < 32; o <<= 1) {
            unsigned int y = __shfl_up_sync(0xFFFFFFFFu, x, o);
            if (lane >= o) x += y;
        }
        const unsigned int excl = x - s;
        const unsigned int pe  = __shfl_sync(0xFFFFFFFFu, excl, tile >> 1);
        const unsigned int po  = __shfl_sync(0xFFFFFFFFu, excl + c0, tile >> 1);
        const unsigned int mcE = __shfl_sync(0xFFFFFFFFu, c0, tile >> 1);
        const unsigned int mcO = __shfl_sync(0xFFFFFFFFu, c1, tile >> 1);
        if (lane == 0) {
            sMeta[0] = (tile & 1) ? po  : pe;
            sMeta[1] = (tile & 1) ? mcO : mcE;
        }
    }
    __syncthreads();
    const unsigned int prefix = sMeta[0];
    const unsigned int cnt    = sMeta[1];

    // --- copy valid block: scratch (L2-resident) -> final position ---
    const float* __restrict__ srcf =
        g_scratch + (batch_base + (size_t)tile * TILE) * 6;
    float* __restrict__ dstf = out + (batch_base + prefix) * 6;
    const unsigned int nF = cnt * 6;                       // floats to copy
    if ((prefix & 1u) == 0u) {
        const float4* __restrict__ s4 = (const float4*)srcf;
        float4* __restrict__ d4 = (float4*)dstf;
        const unsigned int nF4 = nF >> 2;
        for (unsigned int i = tid; i < nF4; i += TPB)
            __stcs(d4 + i, s4[i]);
        if (tid == 0 && (nF & 3u))                         // cnt odd: 2 floats left
            __stcs((float2*)(dstf + (nF4 << 2)),
                   *(const float2*)(srcf + (nF4 << 2)));
    } else {
        const float2* __restrict__ s2 = (const float2*)srcf;
        float2* __restrict__ d2 = (float2*)dstf;
        const unsigned int nF2 = nF >> 1;
        for (unsigned int i = tid; i < nF2; i += TPB)
            __stcs(d2 + i, s2[i]);
    }
}

// ---------------------------------------------------------------------------
extern "C" void kernel_launch(void* const* d_in, const int* in_sizes, int n_in,
                              void* d_out, int out_size) {
    const float* pc = (const float*)d_in[0];   // pointclouds (B, N, 6)
    const float* tf = (const float*)d_in[1];   // task_transform (B, 4, 4)

    const int B = in_sizes[1] / 16;
    const int N = (int)((long long)in_sizes[0] / (6LL * B));
    const int tiles = N / TILE;               // 64

    dim3 grid(tiles, B);
    stage_kernel<<<grid, TPB>>>(pc, tf, (float*)d_out, N, tiles);
    gather_kernel<<<grid, TPB>>>((float*)d_out, N, tiles);
}